// round 12
// baseline (speedup 1.0000x reference)
#include <cuda_runtime.h>

#define TW 64
#define TH 32
#define NT 320
#define S  80   // unified smem row stride (floats)

#define GH 44   /* gray rows, base oy-6; cols base ox-6, 76 wide (38 pairs) */
#define HBH 44  /* hblur rows, base oy-6; cols base ox-4, 72 wide (36 pairs) */
#define MH 38   /* mag rows, base oy-3; cols base ox-3, 70 wide (35 pairs) */
#define NH 36   /* nms rows, base oy-2; cols base ox-2, 68 wide (34 pairs) */

#define LD2(p)      (*(const float2*)(p))
#define ST2(p, v)   (*(float2*)(p) = (v))

__device__ __forceinline__ int reflect2i(int c) {
    return (c < 0) ? -c : ((c > 511) ? 1022 - c : c);
}

__device__ __forceinline__ int decode_off(int k) {
    return k ? (S + 2 - k) : 1;   // 0->1, 1->S+1, 2->S, 3->S-1
}

__global__ __launch_bounds__(NT) void canny_edge_kernel(
    const float* __restrict__ x, float* __restrict__ out)
{
    __shared__ __align__(16) float A[GH * S];   // gray -> blur -> nms
    __shared__ __align__(16) float B[GH * S];   // hblur -> magsq -> colmax

    const int tid = threadIdx.x;
    const int tx = tid % 40;    // pair index 0..39
    const int ty = tid / 40;    // row group 0..7
    const int ox = blockIdx.x * TW;
    const int oy = blockIdx.y * TH;
    const int n  = blockIdx.z;

    const float gk0 = 0.054488685f;
    const float gk1 = 0.244201342f;
    const float gk2 = 0.402619947f;

    const float* c0 = x + ((size_t)n * 3 + 0) * 512 * 512;
    const float* c1 = x + ((size_t)n * 3 + 1) * 512 * 512;
    const float* c2 = x + ((size_t)n * 3 + 2) * 512 * 512;

    const bool interior = (ox >= 6) && (ox + TW + 6 <= 512) &&
                          (oy >= 6) && (oy + TH + 6 <= 512);

    const float t1 = 0.41421356237f;  // tan(22.5 deg)
    const float t2 = 2.41421356237f;  // tan(67.5 deg)

    // ---- Stage 1: grayscale into A (38 pairs) ----
    if (tx < 38) {
        const int cc = 2 * tx;
        if (interior) {
            const int gbase = (oy - 6) * 512 + (ox - 6) + cc;
            for (int lr = ty; lr < GH; lr += 8) {
                const int idx = gbase + lr * 512;
                float2 a0 = LD2(c0 + idx);
                float2 a1 = LD2(c1 + idx);
                float2 a2 = LD2(c2 + idx);
                float2 g;
                g.x = 0.299f * a2.x + 0.587f * a1.x + 0.114f * a0.x;
                g.y = 0.299f * a2.y + 0.587f * a1.y + 0.114f * a0.y;
                ST2(&A[lr * S + cc], g);
            }
        } else {
            const int gxa = reflect2i(ox - 6 + cc);
            const int gxb = reflect2i(ox - 6 + cc + 1);
            for (int lr = ty; lr < GH; lr += 8) {
                int rb = reflect2i(oy - 6 + lr) * 512;
                float2 g;
                g.x = 0.299f * c2[rb + gxa] + 0.587f * c1[rb + gxa] + 0.114f * c0[rb + gxa];
                g.y = 0.299f * c2[rb + gxb] + 0.587f * c1[rb + gxb] + 0.114f * c0[rb + gxb];
                ST2(&A[lr * S + cc], g);
            }
        }
    }
    __syncthreads();

    // ---- Stage 2: horizontal blur -> B (36 pairs) ----
    if (tx < 36) {
        const int cc = 2 * tx;
        for (int lr = ty; lr < HBH; lr += 8) {
            const float* a = &A[lr * S + cc];
            float2 u = LD2(a);
            float2 v = LD2(a + 2);
            float2 w = LD2(a + 4);
            float2 o;
            o.x = gk0 * (u.x + w.x) + gk1 * (u.y + v.y) + gk2 * v.x;
            o.y = gk0 * (u.y + w.y) + gk1 * (v.x + w.x) + gk2 * v.y;
            ST2(&B[lr * S + cc], o);
        }
    }
    __syncthreads();

    // ---- Stage 3: vertical blur -> A (40 rows; rolling 5/chunk; 36 pairs) ----
    if (tx < 36) {
        const int r0 = ty * 5;
        const int c = 2 * tx;
        float2 w0 = LD2(&B[(r0 + 0) * S + c]);
        float2 w1 = LD2(&B[(r0 + 1) * S + c]);
        float2 w2 = LD2(&B[(r0 + 2) * S + c]);
        float2 w3 = LD2(&B[(r0 + 3) * S + c]);
        #pragma unroll
        for (int j = 0; j < 5; j++) {
            float2 w4 = LD2(&B[(r0 + j + 4) * S + c]);
            float2 o;
            o.x = gk0 * (w0.x + w4.x) + gk1 * (w1.x + w3.x) + gk2 * w2.x;
            o.y = gk0 * (w0.y + w4.y) + gk1 * (w1.y + w3.y) + gk2 * w2.y;
            ST2(&A[(r0 + j) * S + c], o);
            w0 = w1; w1 = w2; w2 = w3; w3 = w4;
        }
    }
    __syncthreads();

    // ---- Stage 4: Sobel -> magsq in B (35 pairs); magsq + codes retained in registers ----
    unsigned cwx = 0, cwy = 0;        // 2 bits per row
    float mgx[5], mgy[5];             // retained centers for stage 5
    #pragma unroll
    for (int j = 0; j < 5; j++) { mgx[j] = 0.f; mgy[j] = 0.f; }
    if (interior) {
        if (tx < 35) {
            const int r0 = ty * 5;
            const int c = 2 * tx;
            float2 a0 = LD2(&A[(r0 + 0) * S + c]), b0 = LD2(&A[(r0 + 0) * S + c + 2]);
            float2 a1 = LD2(&A[(r0 + 1) * S + c]), b1 = LD2(&A[(r0 + 1) * S + c + 2]);
            #pragma unroll
            for (int j = 0; j < 5; j++) {
                if (r0 + j < MH) {
                    float2 a2 = LD2(&A[(r0 + j + 2) * S + c]);
                    float2 b2 = LD2(&A[(r0 + j + 2) * S + c + 2]);
                    float sx0 = 0.125f * (b0.x - a0.x) + 0.25f * (b1.x - a1.x) + 0.125f * (b2.x - a2.x);
                    float sy0 = 0.125f * (a2.x - a0.x) + 0.25f * (a2.y - a0.y) + 0.125f * (b2.x - b0.x);
                    float sx1 = 0.125f * (b0.y - a0.y) + 0.25f * (b1.y - a1.y) + 0.125f * (b2.y - a2.y);
                    float sy1 = 0.125f * (a2.y - a0.y) + 0.25f * (b2.x - b0.x) + 0.125f * (b2.y - b0.y);
                    float2 m;
                    m.x = sx0 * sx0 + sy0 * sy0 + 1e-6f;
                    m.y = sx1 * sx1 + sy1 * sy1 + 1e-6f;
                    mgx[j] = m.x; mgy[j] = m.y;
                    float adx0 = fabsf(sx0), ady0 = fabsf(sy0);
                    float adx1 = fabsf(sx1), ady1 = fabsf(sy1);
                    int k0, k1;
                    if (ady0 <= adx0 * t1)      k0 = 0;
                    else if (ady0 >= adx0 * t2) k0 = 2;
                    else                        k0 = ((sx0 > 0.f) == (sy0 > 0.f)) ? 1 : 3;
                    if (ady1 <= adx1 * t1)      k1 = 0;
                    else if (ady1 >= adx1 * t2) k1 = 2;
                    else                        k1 = ((sx1 > 0.f) == (sy1 > 0.f)) ? 1 : 3;
                    cwx |= ((unsigned)k0) << (2 * j);
                    cwy |= ((unsigned)k1) << (2 * j);
                    ST2(&B[(r0 + j) * S + c], m);
                    a0 = a1; b0 = b1;
                    a1 = a2; b1 = b2;
                }
            }
        }
    } else {
        if (tx < 35) {
            #pragma unroll
            for (int sub = 0; sub < 2; sub++) {
                int lc = 2 * tx + sub;
                int gx = ox - 3 + lc;
                bool cv = (unsigned)gx < 512u;
                int cxm = min(max(gx - 1, 0), 511) - (ox - 4);
                int cx0 = min(max(gx,     0), 511) - (ox - 4);
                int cxp = min(max(gx + 1, 0), 511) - (ox - 4);
                unsigned cc = 0;
                #pragma unroll
                for (int k = 0; k < 5; k++) {
                    int lr = ty * 5 + k;
                    if (lr < MH) {
                        int gy = oy - 3 + lr;
                        float m = 0.f;
                        int kk = 0;
                        if (cv && (unsigned)gy < 512u) {
                            int cym = min(max(gy - 1, 0), 511) - (oy - 4);
                            int cy0 = gy - (oy - 4);
                            int cyp = min(max(gy + 1, 0), 511) - (oy - 4);
                            float bmm = A[cym * S + cxm], bm0 = A[cym * S + cx0], bmp = A[cym * S + cxp];
                            float b0m = A[cy0 * S + cxm],                         b0p = A[cy0 * S + cxp];
                            float bpm = A[cyp * S + cxm], bp0 = A[cyp * S + cx0], bpp = A[cyp * S + cxp];
                            float sx = 0.125f * (bmp - bmm) + 0.25f * (b0p - b0m) + 0.125f * (bpp - bpm);
                            float sy = 0.125f * (bpm - bmm) + 0.25f * (bp0 - bm0) + 0.125f * (bpp - bmp);
                            m = sx * sx + sy * sy + 1e-6f;
                            float adx = fabsf(sx), ady = fabsf(sy);
                            if (ady <= adx * t1)       kk = 0;
                            else if (ady >= adx * t2)  kk = 2;
                            else                       kk = ((sx > 0.f) == (sy > 0.f)) ? 1 : 3;
                        }
                        B[lr * S + lc] = m;
                        if (sub == 0) mgx[k] = m; else mgy[k] = m;
                        cc |= ((unsigned)kk) << (2 * k);
                    }
                }
                if (sub == 0) cwx = cc; else cwy = cc;
            }
        }
    }
    __syncthreads();

    // ---- Stage 5: NMS -> A (centers from registers; neighbors from B) ----
    // mag (r, mc) -> A[r-1, mc-1]; valid mc 1..68, r 1..36.
    if (tx < 35) {
        const int c = 2 * tx;
        const int r0 = ty * 5;
        #pragma unroll
        for (int j = 0; j < 5; j++) {
            int r = r0 + j;
            if (r >= 1 && r <= NH && r < MH) {
                int bi = r * S + c;
                if (c > 0) {
                    int off = decode_off((cwx >> (2 * j)) & 3);
                    float m = mgx[j];
                    float pp = B[bi + off], qq = B[bi - off];
                    A[(r - 1) * S + (c - 1)] = (m > pp && m > qq) ? m : 0.f;
                }
                if (c + 1 <= 68) {
                    int off = decode_off((cwy >> (2 * j)) & 3);
                    float m = mgy[j];
                    float pp = B[bi + 1 + off], qq = B[bi + 1 - off];
                    A[(r - 1) * S + c] = (m > pp && m > qq) ? m : 0.f;
                }
            }
        }
    }
    __syncthreads();

    // ---- Stage 6: vertical 5-max -> B (32 rows; rolling 4/chunk; 34 pairs) ----
    if (tx < 34) {
        const int r0 = ty * 4;
        const int c = 2 * tx;
        float2 w0 = LD2(&A[(r0 + 0) * S + c]);
        float2 w1 = LD2(&A[(r0 + 1) * S + c]);
        float2 w2 = LD2(&A[(r0 + 2) * S + c]);
        float2 w3 = LD2(&A[(r0 + 3) * S + c]);
        #pragma unroll
        for (int j = 0; j < 4; j++) {
            float2 w4 = LD2(&A[(r0 + j + 4) * S + c]);
            float2 o;
            o.x = fmaxf(fmaxf(fmaxf(w0.x, w1.x), fmaxf(w2.x, w3.x)), w4.x);
            o.y = fmaxf(fmaxf(fmaxf(w0.y, w1.y), fmaxf(w2.y, w3.y)), w4.y);
            ST2(&B[(r0 + j) * S + c], o);
            w0 = w1; w1 = w2; w2 = w3; w3 = w4;
        }
    }
    __syncthreads();

    // ---- Stage 7: horizontal 5-max + final sqrt (32 pairs) ----
    if (tx < 32) {
        const int c = 2 * tx;
        for (int lr = ty; lr < TH; lr += 8) {
            float2 a = LD2(&B[lr * S + c]);
            float2 b = LD2(&B[lr * S + c + 2]);
            float2 d = LD2(&B[lr * S + c + 4]);
            float2 o;
            o.x = sqrtf(fmaxf(fmaxf(fmaxf(a.x, a.y), fmaxf(b.x, b.y)), d.x));
            o.y = sqrtf(fmaxf(fmaxf(fmaxf(a.y, b.x), fmaxf(b.y, d.x)), d.y));
            ST2(&out[((size_t)n * 512 + (oy + lr)) * 512 + (ox + c)], o);
        }
    }
}

extern "C" void kernel_launch(void* const* d_in, const int* in_sizes, int n_in,
                              void* d_out, int out_size)
{
    const float* x = (const float*)d_in[0];
    float* out = (float*)d_out;
    dim3 grid(512 / TW, 512 / TH, 32);
    canny_edge_kernel<<<grid, NT>>>(x, out);
}

// round 14
// speedup vs baseline: 1.0672x; 1.0672x over previous
#include <cuda_runtime.h>

#define TW 64
#define TH 32
#define NT 320
#define S  80   // unified smem row stride (floats)

#define GH 44   /* gray rows, base oy-6; cols base ox-6, 76 wide (38 pairs) */
#define MH 38   /* mag rows, base oy-3; cols base ox-3, 70 wide (35 pairs) */
#define NH 36   /* nms rows, base oy-2; cols base ox-2, 68 wide (34 pairs) */

#define LD2(p)      (*(const float2*)(p))
#define ST2(p, v)   (*(float2*)(p) = (v))

__device__ __forceinline__ int reflect2i(int c) {
    return (c < 0) ? -c : ((c > 511) ? 1022 - c : c);
}

__device__ __forceinline__ int decode_off(int k) {
    return k ? (S + 2 - k) : 1;   // 0->1, 1->S+1, 2->S, 3->S-1
}

__global__ __launch_bounds__(NT) void canny_edge_kernel(
    const float* __restrict__ x, float* __restrict__ out)
{
    __shared__ __align__(16) float A[GH * S];   // gray -> magsq -> colmax
    __shared__ __align__(16) float B[GH * S];   // blur -> nms

    const int tid = threadIdx.x;
    const int tx = tid % 40;    // pair index 0..39
    const int ty = tid / 40;    // row group 0..7
    const int ox = blockIdx.x * TW;
    const int oy = blockIdx.y * TH;
    const int n  = blockIdx.z;

    const float gk0 = 0.054488685f;
    const float gk1 = 0.244201342f;
    const float gk2 = 0.402619947f;

    const float* c0 = x + ((size_t)n * 3 + 0) * 512 * 512;
    const float* c1 = x + ((size_t)n * 3 + 1) * 512 * 512;
    const float* c2 = x + ((size_t)n * 3 + 2) * 512 * 512;

    const bool interior = (ox >= 6) && (ox + TW + 6 <= 512) &&
                          (oy >= 6) && (oy + TH + 6 <= 512);

    const float t1 = 0.41421356237f;  // tan(22.5 deg)
    const float t2 = 2.41421356237f;  // tan(67.5 deg)

    // ---- Stage 1: grayscale into A (38 pairs) ----
    if (tx < 38) {
        const int cc = 2 * tx;
        if (interior) {
            const int gbase = (oy - 6) * 512 + (ox - 6) + cc;
            for (int lr = ty; lr < GH; lr += 8) {
                const int idx = gbase + lr * 512;
                float2 a0 = LD2(c0 + idx);
                float2 a1 = LD2(c1 + idx);
                float2 a2 = LD2(c2 + idx);
                float2 g;
                g.x = 0.299f * a2.x + 0.587f * a1.x + 0.114f * a0.x;
                g.y = 0.299f * a2.y + 0.587f * a1.y + 0.114f * a0.y;
                ST2(&A[lr * S + cc], g);
            }
        } else {
            const int gxa = reflect2i(ox - 6 + cc);
            const int gxb = reflect2i(ox - 6 + cc + 1);
            for (int lr = ty; lr < GH; lr += 8) {
                int rb = reflect2i(oy - 6 + lr) * 512;
                float2 g;
                g.x = 0.299f * c2[rb + gxa] + 0.587f * c1[rb + gxa] + 0.114f * c0[rb + gxa];
                g.y = 0.299f * c2[rb + gxb] + 0.587f * c1[rb + gxb] + 0.114f * c0[rb + gxb];
                ST2(&A[lr * S + cc], g);
            }
        }
    }
    __syncthreads();

    // ---- Stage 2+3 fused: separable Gaussian, hblur on the fly -> blur in B ----
    // blur row b (base oy-4) = sum_v gk[v]*hblur(gray row b+v); 40 rows, 36 pairs.
    if (tx < 36) {
        const int c = 2 * tx;
        const int r0 = ty * 5;
        float2 h0, h1, h2, h3, h4;
        #define HBLUR(g, o_) { const float* a_ = &A[(g) * S + c]; \
            float2 u_ = LD2(a_), v_ = LD2(a_ + 2), w_ = LD2(a_ + 4); \
            o_.x = gk0 * (u_.x + w_.x) + gk1 * (u_.y + v_.y) + gk2 * v_.x; \
            o_.y = gk0 * (u_.y + w_.y) + gk1 * (v_.x + w_.x) + gk2 * v_.y; }
        HBLUR(r0 + 0, h0);
        HBLUR(r0 + 1, h1);
        HBLUR(r0 + 2, h2);
        HBLUR(r0 + 3, h3);
        #pragma unroll
        for (int j = 0; j < 5; j++) {
            HBLUR(r0 + j + 4, h4);
            float2 o;
            o.x = gk0 * (h0.x + h4.x) + gk1 * (h1.x + h3.x) + gk2 * h2.x;
            o.y = gk0 * (h0.y + h4.y) + gk1 * (h1.y + h3.y) + gk2 * h2.y;
            ST2(&B[(r0 + j) * S + c], o);
            h0 = h1; h1 = h2; h2 = h3; h3 = h4;
        }
        #undef HBLUR
    }
    __syncthreads();

    // ---- Stage 4: Sobel on blur(B) -> magsq in A (35 pairs); codes in registers ----
    unsigned cwx = 0, cwy = 0;   // 2 bits per row, up to 5 rows
    if (interior) {
        if (tx < 35) {
            const int r0 = ty * 5;
            const int cnt = min(5, MH - r0);   // ty==7 -> 3
            const int c = 2 * tx;
            float2 a0 = LD2(&B[(r0 + 0) * S + c]), b0 = LD2(&B[(r0 + 0) * S + c + 2]);
            float2 a1 = LD2(&B[(r0 + 1) * S + c]), b1 = LD2(&B[(r0 + 1) * S + c + 2]);
            for (int j = 0; j < cnt; j++) {
                float2 a2 = LD2(&B[(r0 + j + 2) * S + c]);
                float2 b2 = LD2(&B[(r0 + j + 2) * S + c + 2]);
                float sx0 = 0.125f * (b0.x - a0.x) + 0.25f * (b1.x - a1.x) + 0.125f * (b2.x - a2.x);
                float sy0 = 0.125f * (a2.x - a0.x) + 0.25f * (a2.y - a0.y) + 0.125f * (b2.x - b0.x);
                float sx1 = 0.125f * (b0.y - a0.y) + 0.25f * (b1.y - a1.y) + 0.125f * (b2.y - a2.y);
                float sy1 = 0.125f * (a2.y - a0.y) + 0.25f * (b2.x - b0.x) + 0.125f * (b2.y - b0.y);
                float2 m;
                m.x = sx0 * sx0 + sy0 * sy0 + 1e-6f;
                m.y = sx1 * sx1 + sy1 * sy1 + 1e-6f;
                float adx0 = fabsf(sx0), ady0 = fabsf(sy0);
                float adx1 = fabsf(sx1), ady1 = fabsf(sy1);
                int k0, k1;
                if (ady0 <= adx0 * t1)      k0 = 0;
                else if (ady0 >= adx0 * t2) k0 = 2;
                else                        k0 = ((sx0 > 0.f) == (sy0 > 0.f)) ? 1 : 3;
                if (ady1 <= adx1 * t1)      k1 = 0;
                else if (ady1 >= adx1 * t2) k1 = 2;
                else                        k1 = ((sx1 > 0.f) == (sy1 > 0.f)) ? 1 : 3;
                cwx |= ((unsigned)k0) << (2 * j);
                cwy |= ((unsigned)k1) << (2 * j);
                ST2(&A[(r0 + j) * S + c], m);
                a0 = a1; b0 = b1;
                a1 = a2; b1 = b2;
            }
        }
    } else {
        if (tx < 35) {
            #pragma unroll
            for (int sub = 0; sub < 2; sub++) {
                int lc = 2 * tx + sub;
                int gx = ox - 3 + lc;
                bool cv = (unsigned)gx < 512u;
                int cxm = min(max(gx - 1, 0), 511) - (ox - 4);
                int cx0 = min(max(gx,     0), 511) - (ox - 4);
                int cxp = min(max(gx + 1, 0), 511) - (ox - 4);
                unsigned cc = 0;
                #pragma unroll
                for (int k = 0; k < 5; k++) {
                    int lr = ty * 5 + k;
                    if (lr < MH) {
                        int gy = oy - 3 + lr;
                        float m = 0.f;
                        int kk = 0;
                        if (cv && (unsigned)gy < 512u) {
                            int cym = min(max(gy - 1, 0), 511) - (oy - 4);
                            int cy0 = gy - (oy - 4);
                            int cyp = min(max(gy + 1, 0), 511) - (oy - 4);
                            float bmm = B[cym * S + cxm], bm0 = B[cym * S + cx0], bmp = B[cym * S + cxp];
                            float b0m = B[cy0 * S + cxm],                         b0p = B[cy0 * S + cxp];
                            float bpm = B[cyp * S + cxm], bp0 = B[cyp * S + cx0], bpp = B[cyp * S + cxp];
                            float sx = 0.125f * (bmp - bmm) + 0.25f * (b0p - b0m) + 0.125f * (bpp - bpm);
                            float sy = 0.125f * (bpm - bmm) + 0.25f * (bp0 - bm0) + 0.125f * (bpp - bmp);
                            m = sx * sx + sy * sy + 1e-6f;
                            float adx = fabsf(sx), ady = fabsf(sy);
                            if (ady <= adx * t1)       kk = 0;
                            else if (ady >= adx * t2)  kk = 2;
                            else                       kk = ((sx > 0.f) == (sy > 0.f)) ? 1 : 3;
                        }
                        A[lr * S + lc] = m;
                        cc |= ((unsigned)kk) << (2 * k);
                    }
                }
                if (sub == 0) cwx = cc; else cwy = cc;
            }
        }
    }
    __syncthreads();

    // ---- Stage 5: NMS on magsq(A) -> nms in B (codes from registers) ----
    // mag (r, mc) -> B[r-1, mc-1]; valid mc 1..68, r 1..36.
    if (tx < 35) {
        const int c = 2 * tx;
        const int r0 = ty * 5;
        #pragma unroll
        for (int j = 0; j < 5; j++) {
            int r = r0 + j;
            if (r >= 1 && r <= NH && r < MH) {
                int bi = r * S + c;
                if (c > 0) {
                    int off = decode_off((cwx >> (2 * j)) & 3);
                    float m = A[bi];
                    float pp = A[bi + off], qq = A[bi - off];
                    B[(r - 1) * S + (c - 1)] = (m > pp && m > qq) ? m : 0.f;
                }
                if (c + 1 <= 68) {
                    int off = decode_off((cwy >> (2 * j)) & 3);
                    float m = A[bi + 1];
                    float pp = A[bi + 1 + off], qq = A[bi + 1 - off];
                    B[(r - 1) * S + c] = (m > pp && m > qq) ? m : 0.f;
                }
            }
        }
    }
    __syncthreads();

    // ---- Stage 6: vertical 5-max on nms(B) -> colmax in A (32 rows; 34 pairs) ----
    if (tx < 34) {
        const int r0 = ty * 4;
        const int c = 2 * tx;
        float2 w0 = LD2(&B[(r0 + 0) * S + c]);
        float2 w1 = LD2(&B[(r0 + 1) * S + c]);
        float2 w2 = LD2(&B[(r0 + 2) * S + c]);
        float2 w3 = LD2(&B[(r0 + 3) * S + c]);
        #pragma unroll
        for (int j = 0; j < 4; j++) {
            float2 w4 = LD2(&B[(r0 + j + 4) * S + c]);
            float2 o;
            o.x = fmaxf(fmaxf(fmaxf(w0.x, w1.x), fmaxf(w2.x, w3.x)), w4.x);
            o.y = fmaxf(fmaxf(fmaxf(w0.y, w1.y), fmaxf(w2.y, w3.y)), w4.y);
            ST2(&A[(r0 + j) * S + c], o);
            w0 = w1; w1 = w2; w2 = w3; w3 = w4;
        }
    }
    __syncthreads();

    // ---- Stage 7: horizontal 5-max on colmax(A) + final sqrt (32 pairs) ----
    if (tx < 32) {
        const int c = 2 * tx;
        for (int lr = ty; lr < TH; lr += 8) {
            float2 a = LD2(&A[lr * S + c]);
            float2 b = LD2(&A[lr * S + c + 2]);
            float2 d = LD2(&A[lr * S + c + 4]);
            float2 o;
            o.x = sqrtf(fmaxf(fmaxf(fmaxf(a.x, a.y), fmaxf(b.x, b.y)), d.x));
            o.y = sqrtf(fmaxf(fmaxf(fmaxf(a.y, b.x), fmaxf(b.y, d.x)), d.y));
            ST2(&out[((size_t)n * 512 + (oy + lr)) * 512 + (ox + c)], o);
        }
    }
}

extern "C" void kernel_launch(void* const* d_in, const int* in_sizes, int n_in,
                              void* d_out, int out_size)
{
    const float* x = (const float*)d_in[0];
    float* out = (float*)d_out;
    dim3 grid(512 / TW, 512 / TH, 32);
    canny_edge_kernel<<<grid, NT>>>(x, out);
}